// round 12
// baseline (speedup 1.0000x reference)
#include <cuda_runtime.h>
#include <cuda_bf16.h>
#include <math.h>
#include <cstdint>

#define B_  32
#define T_  64
#define S_  64
#define V_  32000
#define E_  512
#define H_  512
#define SD_ 1024
#define SCALE_ 0.04419417382415922f  // 1/sqrt(512)

#define NB 128
#define NT 256
#define NW (NB * 8)     // 1024 warps
#define XST 1540        // X row stride in floats; 1540*4 bytes, 16B aligned, conflict-free
#define XBYTES (B_ * XST * 4)

__device__ float g_h[2][B_ * H_];
__device__ float g_c[B_ * H_];
__device__ float g_hhat[B_ * H_];
__device__ float g_Q[B_ * S_ * H_];
__device__ float g_GT[H_ * B_ * S_];
__device__ float g_qb[B_ * S_];
__device__ float g_sc[B_ * S_];
__device__ unsigned g_arrive;

__device__ __nv_bfloat16 g_outs_hi[T_ * B_ * H_];
__device__ __nv_bfloat16 g_outs_lo[T_ * B_ * H_];
__device__ __nv_bfloat16 g_W_hi[(size_t)V_ * H_];
__device__ __nv_bfloat16 g_W_lo[(size_t)V_ * H_];

__device__ __forceinline__ float sigmoidf_(float x) {
    return 1.0f / (1.0f + __expf(-x));
}

__device__ __forceinline__ void grid_sync(unsigned target) {
    __syncthreads();
    if (threadIdx.x == 0) {
        __threadfence();
        atomicAdd(&g_arrive, 1u);
        unsigned v;
        do {
            asm volatile("ld.global.acquire.gpu.u32 %0, [%1];"
                         : "=r"(v) : "l"(&g_arrive));
        } while (v < target);
    }
    __syncthreads();
}

__device__ __forceinline__ void cp16(void* dst_smem, const void* src) {
    uint32_t d = (uint32_t)__cvta_generic_to_shared(dst_smem);
    asm volatile("cp.async.cg.shared.global [%0], [%1], 16;" :: "r"(d), "l"(src));
}

// ---------------- init ----------------
__global__ void init_kernel(const float* __restrict__ hinit,
                            const float* __restrict__ iff) {
    if (blockIdx.x == 0 && threadIdx.x == 0) g_arrive = 0u;
    int idx = blockIdx.x * blockDim.x + threadIdx.x;
    if (idx < B_ * H_) {
        int m = idx & (H_ - 1);
        g_h[0][idx] = hinit[m];
        g_c[idx]    = hinit[H_ + m];
        g_hhat[idx] = iff[m];
    }
}

// ---------------- Wfc -> bf16 hi/lo ----------------
__global__ void __launch_bounds__(256) wconv_kernel(const float* __restrict__ Wfc) {
    const size_t n4 = (size_t)V_ * H_ / 4;
    for (size_t i = blockIdx.x * 256 + threadIdx.x; i < n4; i += (size_t)gridDim.x * 256) {
        float4 wv = ((const float4*)Wfc)[i];
        float w[4] = {wv.x, wv.y, wv.z, wv.w};
        __nv_bfloat16 hi[4], lo[4];
        #pragma unroll
        for (int u = 0; u < 4; ++u) {
            hi[u] = __float2bfloat16(w[u]);
            lo[u] = __float2bfloat16(w[u] - __bfloat162float(hi[u]));
        }
        *(ushort4*)&g_W_hi[i * 4] = make_ushort4(
            __bfloat16_as_ushort(hi[0]), __bfloat16_as_ushort(hi[1]),
            __bfloat16_as_ushort(hi[2]), __bfloat16_as_ushort(hi[3]));
        *(ushort4*)&g_W_lo[i * 4] = make_ushort4(
            __bfloat16_as_ushort(lo[0]), __bfloat16_as_ushort(lo[1]),
            __bfloat16_as_ushort(lo[2]), __bfloat16_as_ushort(lo[3]));
    }
}

// ---------------- qb[r] = bp . src[r] ----------------
__global__ void __launch_bounds__(256) qb_kernel(
    const float* __restrict__ src, const float* __restrict__ bp)
{
    const int w = threadIdx.x >> 5, lane = threadIdx.x & 31;
    const int r = blockIdx.x * 8 + w;
    const float4* sr = (const float4*)(src + (size_t)r * SD_);
    const float4* bv = (const float4*)bp;
    float a = 0.f;
    #pragma unroll
    for (int i = lane; i < SD_ / 4; i += 32) {
        float4 x = sr[i], b = bv[i];
        a += x.x*b.x + x.y*b.y + x.z*b.z + x.w*b.w;
    }
    #pragma unroll
    for (int o = 16; o; o >>= 1) a += __shfl_xor_sync(0xFFFFFFFFu, a, o);
    if (lane == 0) g_qb[r] = a;
}

// ---------------- Q = src @ Wp (NN) ----------------
#define PBM 64
#define PBN 64
#define PBK 16
__global__ void __launch_bounds__(256) qgemm_kernel(
    const float* __restrict__ src, const float* __restrict__ Wp)
{
    __shared__ float As[PBK][PBM + 4];
    __shared__ float Bs[PBK][PBN + 4];
    const int tid = threadIdx.x;
    const int tx = tid & 15, ty = tid >> 4;
    const int r0 = blockIdx.y * PBM;
    const int v0 = blockIdx.x * PBN;
    const int a_row = tid >> 2, a_k = (tid & 3) * 4;
    const int b_k = tid >> 4, b_n = (tid & 15) * 4;

    float acc[4][4] = {};
    for (int k0 = 0; k0 < SD_; k0 += PBK) {
        float4 a = *(const float4*)&src[(size_t)(r0 + a_row) * SD_ + k0 + a_k];
        As[a_k + 0][a_row] = a.x; As[a_k + 1][a_row] = a.y;
        As[a_k + 2][a_row] = a.z; As[a_k + 3][a_row] = a.w;
        *(float4*)&Bs[b_k][b_n] =
            *(const float4*)&Wp[(size_t)(k0 + b_k) * H_ + v0 + b_n];
        __syncthreads();
        #pragma unroll
        for (int k = 0; k < PBK; ++k) {
            float4 av = *(const float4*)&As[k][ty * 4];
            float4 bv = *(const float4*)&Bs[k][tx * 4];
            acc[0][0]+=av.x*bv.x; acc[0][1]+=av.x*bv.y; acc[0][2]+=av.x*bv.z; acc[0][3]+=av.x*bv.w;
            acc[1][0]+=av.y*bv.x; acc[1][1]+=av.y*bv.y; acc[1][2]+=av.y*bv.z; acc[1][3]+=av.y*bv.w;
            acc[2][0]+=av.z*bv.x; acc[2][1]+=av.z*bv.y; acc[2][2]+=av.z*bv.z; acc[2][3]+=av.z*bv.w;
            acc[3][0]+=av.w*bv.x; acc[3][1]+=av.w*bv.y; acc[3][2]+=av.w*bv.z; acc[3][3]+=av.w*bv.w;
        }
        __syncthreads();
    }
    #pragma unroll
    for (int i = 0; i < 4; ++i) {
        float4 res = make_float4(acc[i][0], acc[i][1], acc[i][2], acc[i][3]);
        *(float4*)&g_Q[(size_t)(r0 + ty * 4 + i) * H_ + v0 + tx * 4] = res;
    }
}

// ---------------- GT[j][r] = Wah[j,512:1536] . src[r] (NT) ----------------
__global__ void __launch_bounds__(256) gtgemm_kernel(
    const float* __restrict__ Wah, const float* __restrict__ src)
{
    __shared__ float As[PBK][PBM + 4];
    __shared__ float Bs[PBK][PBN + 4];
    const int tid = threadIdx.x;
    const int tx = tid & 15, ty = tid >> 4;
    const int j0 = blockIdx.y * PBM;
    const int r0 = blockIdx.x * PBN;
    const int ld_row = tid >> 2, ld_k = (tid & 3) * 4;

    float acc[4][4] = {};
    for (int k0 = 0; k0 < SD_; k0 += PBK) {
        float4 a = *(const float4*)&Wah[(size_t)(j0 + ld_row) * (H_ + SD_) + H_ + k0 + ld_k];
        float4 b = *(const float4*)&src[(size_t)(r0 + ld_row) * SD_ + k0 + ld_k];
        As[ld_k + 0][ld_row] = a.x; As[ld_k + 1][ld_row] = a.y;
        As[ld_k + 2][ld_row] = a.z; As[ld_k + 3][ld_row] = a.w;
        Bs[ld_k + 0][ld_row] = b.x; Bs[ld_k + 1][ld_row] = b.y;
        Bs[ld_k + 2][ld_row] = b.z; Bs[ld_k + 3][ld_row] = b.w;
        __syncthreads();
        #pragma unroll
        for (int k = 0; k < PBK; ++k) {
            float4 av = *(const float4*)&As[k][ty * 4];
            float4 bv = *(const float4*)&Bs[k][tx * 4];
            acc[0][0]+=av.x*bv.x; acc[0][1]+=av.x*bv.y; acc[0][2]+=av.x*bv.z; acc[0][3]+=av.x*bv.w;
            acc[1][0]+=av.y*bv.x; acc[1][1]+=av.y*bv.y; acc[1][2]+=av.y*bv.z; acc[1][3]+=av.y*bv.w;
            acc[2][0]+=av.z*bv.x; acc[2][1]+=av.z*bv.y; acc[2][2]+=av.z*bv.z; acc[2][3]+=av.z*bv.w;
            acc[3][0]+=av.w*bv.x; acc[3][1]+=av.w*bv.y; acc[3][2]+=av.w*bv.z; acc[3][3]+=av.w*bv.w;
        }
        __syncthreads();
    }
    #pragma unroll
    for (int i = 0; i < 4; ++i) {
        float4 res = make_float4(acc[i][0], acc[i][1], acc[i][2], acc[i][3]);
        *(float4*)&g_GT[(size_t)(j0 + ty * 4 + i) * (B_ * S_) + r0 + tx * 4] = res;
    }
}

// ================= persistent recurrence kernel =================
__global__ void __launch_bounds__(NT) step_kernel(
    const int* __restrict__ trg, const float* __restrict__ emb,
    const float* __restrict__ W_ih, const float* __restrict__ b_ih,
    const float* __restrict__ W_hh, const float* __restrict__ b_hh,
    const float* __restrict__ Wah, const float* __restrict__ bah,
    float* __restrict__ out)
{
    extern __shared__ float Xs[];       // [32][XST]
    __shared__ int   tok[B_];
    __shared__ float sp[B_][S_];
    __shared__ float part[8][4][B_];    // per-warp partial gates

    const int w    = threadIdx.x >> 5;
    const int lane = threadIdx.x & 31;
    const int gw   = blockIdx.x * 8 + w;
    unsigned bar = 0;

    const float4* Wi4 = (const float4*)W_ih;  // row stride 256 float4
    const float4* Wh4 = (const float4*)W_hh;  // row stride 128 float4

    for (int t = 0; t < T_; ++t) {
        if (threadIdx.x < B_) tok[threadIdx.x] = trg[threadIdx.x * T_ + t];
        __syncthreads();

        const float* __restrict__ h_in  = g_h[t & 1];
        float*       __restrict__ h_out = g_h[(t & 1) ^ 1];

        // ---- phase 1: stage X = [x_t | h_hat | h_prev] once, then GEMV
        for (int b = 0; b < B_; ++b) {
            for (int k = threadIdx.x; k < 1536; k += NT) {
                float v;
                if (k < 512)       v = emb[(size_t)tok[b] * E_ + k];
                else if (k < 1024) v = g_hhat[b * H_ + (k - 512)];
                else               v = h_in[b * H_ + (k - 1024)];
                Xs[b * XST + k] = v;
            }
        }
        __syncthreads();

        {
            const int m  = gw >> 1;
            const int kh = gw & 1;
            const float4* Xr = (const float4*)(Xs + lane * XST);
            float a0 = 0.f, a1 = 0.f, a2 = 0.f, a3 = 0.f;
            const size_t j0 = m, j1 = H_ + m, j2 = 2*H_ + m, j3 = 3*H_ + m;

            if (kh == 0) {
                #pragma unroll 4
                for (int k4 = 0; k4 < 192; ++k4) {
                    float4 x  = Xr[k4];
                    float4 w0 = Wi4[j0 * 256 + k4];
                    float4 w1 = Wi4[j1 * 256 + k4];
                    float4 w2 = Wi4[j2 * 256 + k4];
                    float4 w3 = Wi4[j3 * 256 + k4];
                    a0 += x.x*w0.x + x.y*w0.y + x.z*w0.z + x.w*w0.w;
                    a1 += x.x*w1.x + x.y*w1.y + x.z*w1.z + x.w*w1.w;
                    a2 += x.x*w2.x + x.y*w2.y + x.z*w2.z + x.w*w2.w;
                    a3 += x.x*w3.x + x.y*w3.y + x.z*w3.z + x.w*w3.w;
                }
            } else {
                #pragma unroll 4
                for (int k4 = 192; k4 < 256; ++k4) {
                    float4 x  = Xr[k4];
                    float4 w0 = Wi4[j0 * 256 + k4];
                    float4 w1 = Wi4[j1 * 256 + k4];
                    float4 w2 = Wi4[j2 * 256 + k4];
                    float4 w3 = Wi4[j3 * 256 + k4];
                    a0 += x.x*w0.x + x.y*w0.y + x.z*w0.z + x.w*w0.w;
                    a1 += x.x*w1.x + x.y*w1.y + x.z*w1.z + x.w*w1.w;
                    a2 += x.x*w2.x + x.y*w2.y + x.z*w2.z + x.w*w2.w;
                    a3 += x.x*w3.x + x.y*w3.y + x.z*w3.z + x.w*w3.w;
                }
                #pragma unroll 4
                for (int k4 = 256; k4 < 384; ++k4) {
                    float4 x  = Xr[k4];
                    float4 w0 = Wh4[j0 * 128 + (k4 - 256)];
                    float4 w1 = Wh4[j1 * 128 + (k4 - 256)];
                    float4 w2 = Wh4[j2 * 128 + (k4 - 256)];
                    float4 w3 = Wh4[j3 * 128 + (k4 - 256)];
                    a0 += x.x*w0.x + x.y*w0.y + x.z*w0.z + x.w*w0.w;
                    a1 += x.x*w1.x + x.y*w1.y + x.z*w1.z + x.w*w1.w;
                    a2 += x.x*w2.x + x.y*w2.y + x.z*w2.z + x.w*w2.w;
                    a3 += x.x*w3.x + x.y*w3.y + x.z*w3.z + x.w*w3.w;
                }
            }
            part[w][0][lane] = a0;
            part[w][1][lane] = a1;
            part[w][2][lane] = a2;
            part[w][3][lane] = a3;
        }
        __syncthreads();

        if (threadIdx.x < 128) {
            const int mi = threadIdx.x >> 5;
            const int b  = threadIdx.x & 31;
            const int m  = blockIdx.x * 4 + mi;
            float vi = part[2*mi][0][b] + part[2*mi+1][0][b] + b_ih[m]       + b_hh[m];
            float vf = part[2*mi][1][b] + part[2*mi+1][1][b] + b_ih[H_+m]   + b_hh[H_+m];
            float vg = part[2*mi][2][b] + part[2*mi+1][2][b] + b_ih[2*H_+m] + b_hh[2*H_+m];
            float vo = part[2*mi][3][b] + part[2*mi+1][3][b] + b_ih[3*H_+m] + b_hh[3*H_+m];
            float ig = sigmoidf_(vi);
            float fg = sigmoidf_(vf);
            float gg = tanhf(vg);
            float og = sigmoidf_(vo);
            float cn = fg * g_c[b * H_ + m] + ig * gg;
            g_c[b * H_ + m] = cn;
            h_out[b * H_ + m] = og * tanhf(cn);
        }
        grid_sync(++bar * NB);

        // ---- phase 2: scores
        {
            const float4* H4 = (const float4*)h_out;
            for (int r = gw; r < B_ * S_; r += NW) {
                const int b = r >> 6;
                const float4* qv = (const float4*)(g_Q + (size_t)r * H_);
                float a = 0.f;
                #pragma unroll
                for (int i = lane; i < H_ / 4; i += 32) {
                    float4 h4 = H4[b * 128 + i], q4 = qv[i];
                    a += h4.x*q4.x + h4.y*q4.y + h4.z*q4.z + h4.w*q4.w;
                }
                #pragma unroll
                for (int o = 16; o; o >>= 1) a += __shfl_xor_sync(0xFFFFFFFFu, a, o);
                if (lane == 0) g_sc[r] = (a + g_qb[r]) * SCALE_;
            }
        }
        grid_sync(++bar * NB);

        // ---- phase 3: softmax + h_hat
        {
            #pragma unroll
            for (int bb = w * 4; bb < w * 4 + 4; ++bb) {
                float v0 = g_sc[bb * S_ + lane], v1 = g_sc[bb * S_ + 32 + lane];
                float mx = fmaxf(v0, v1);
                #pragma unroll
                for (int o = 16; o; o >>= 1)
                    mx = fmaxf(mx, __shfl_xor_sync(0xFFFFFFFFu, mx, o));
                float e0 = __expf(v0 - mx), e1 = __expf(v1 - mx);
                float sm = e0 + e1;
                #pragma unroll
                for (int o = 16; o; o >>= 1) sm += __shfl_xor_sync(0xFFFFFFFFu, sm, o);
                float inv = 1.0f / sm;
                sp[bb][lane] = e0 * inv;
                sp[bb][lane + 32] = e1 * inv;
            }
            __syncthreads();

            const float4* H4 = (const float4*)h_out;
            for (int q = w; q < 16; q += 8) {
                const int j = blockIdx.x + NB * (q >> 2);
                const int b0 = (q & 3) << 3;
                const float4* Wr = (const float4*)(Wah + (size_t)j * (H_ + SD_));
                float acc[8] = {};
                #pragma unroll
                for (int kk = 0; kk < 4; ++kk) {
                    const int i = (kk << 5) + lane;
                    float4 ww = Wr[i];
                    #pragma unroll
                    for (int u = 0; u < 8; ++u) {
                        float4 a = H4[(b0 + u) * 128 + i];
                        acc[u] += a.x*ww.x + a.y*ww.y + a.z*ww.z + a.w*ww.w;
                    }
                }
                const float* gt = g_GT + (size_t)j * (B_ * S_);
                #pragma unroll
                for (int u = 0; u < 8; ++u) {
                    const int b = b0 + u;
                    float g0 = gt[b * S_ + lane];
                    float g1 = gt[b * S_ + 32 + lane];
                    acc[u] += sp[b][lane] * g0 + sp[b][lane + 32] * g1;
                }
                #pragma unroll
                for (int o = 16; o; o >>= 1)
                    #pragma unroll
                    for (int u = 0; u < 8; ++u)
                        acc[u] += __shfl_xor_sync(0xFFFFFFFFu, acc[u], o);
                if (lane < 8) {
                    float av = 0.f;
                    #pragma unroll
                    for (int u = 0; u < 8; ++u)
                        if (lane == u) av = acc[u];
                    const int b = b0 + lane;
                    float v = tanhf(av + bah[j]);
                    g_hhat[b * H_ + j] = v;
                    size_t oidx = ((size_t)t * B_ + b) * H_ + j;
                    __nv_bfloat16 hi = __float2bfloat16(v);
                    g_outs_hi[oidx] = hi;
                    g_outs_lo[oidx] = __float2bfloat16(v - __bfloat162float(hi));
                }
            }
        }
        grid_sync(++bar * NB);
    }

    size_t base = (size_t)B_ * T_ * V_;
    for (int idx = blockIdx.x * NT + threadIdx.x; idx < B_ * H_; idx += NB * NT) {
        out[base + idx]               = g_h[0][idx];
        out[base + B_ * H_ + idx]     = g_c[idx];
        out[base + 2 * B_ * H_ + idx] = g_hhat[idx];
    }
}

// ================= final GEMM: bf16 hi/lo, cp.async double-buffered =================
#define FGS 5120                 // elements per 128x40 array
#define FG_STAGE (4 * FGS)       // Ahi, Alo, Bhi, Blo per stage
#define FG_SMEM (2 * FG_STAGE * 2)  // bytes (81920)

__device__ __forceinline__ void fg_load(__nv_bfloat16* base, int k0,
                                        int r0, int v0, int tid) {
    // 512 items = 128 rows x 4 16B-quads; each item stages all 4 arrays
    #pragma unroll
    for (int i = 0; i < 2; ++i) {
        int idx = i * 256 + tid;
        int row = idx >> 2, q = idx & 3;
        int off = row * 40 + q * 8;
        cp16(base + 0*FGS + off, g_outs_hi + (size_t)(r0 + row) * H_ + k0 + q*8);
        cp16(base + 1*FGS + off, g_outs_lo + (size_t)(r0 + row) * H_ + k0 + q*8);
        cp16(base + 2*FGS + off, g_W_hi   + (size_t)(v0 + row) * H_ + k0 + q*8);
        cp16(base + 3*FGS + off, g_W_lo   + (size_t)(v0 + row) * H_ + k0 + q*8);
    }
    asm volatile("cp.async.commit_group;");
}

__global__ void __launch_bounds__(256) fgemm_kernel(
    const float* __restrict__ bfc, float* __restrict__ out)
{
    extern __shared__ __nv_bfloat16 fsm[];
    const int tid  = threadIdx.x;
    const int w    = tid >> 5;
    const int lane = tid & 31;
    const int r0 = blockIdx.y * 128;
    const int v0 = blockIdx.x * 128;
    const int wm0 = (w >> 1) * 32;
    const int wn0 = (w & 1) * 64;

    float acc[2][8][4];
    #pragma unroll
    for (int mt = 0; mt < 2; ++mt)
        #pragma unroll
        for (int nt = 0; nt < 8; ++nt)
            #pragma unroll
            for (int i = 0; i < 4; ++i) acc[mt][nt][i] = 0.f;

    fg_load(fsm, 0, r0, v0, tid);

    for (int it = 0; it < 16; ++it) {
        if (it + 1 < 16) {
            fg_load(fsm + ((it + 1) & 1) * FG_STAGE, (it + 1) * 32, r0, v0, tid);
            asm volatile("cp.async.wait_group 1;");
        } else {
            asm volatile("cp.async.wait_group 0;");
        }
        __syncthreads();

        __nv_bfloat16* base = fsm + (it & 1) * FG_STAGE;
        const __nv_bfloat16* Ab[2] = { base, base + FGS };
        const __nv_bfloat16* Bb[2] = { base + 2*FGS, base + 3*FGS };
        const int sec = lane >> 3;

        #pragma unroll
        for (int ks = 0; ks < 32; ks += 16) {
            uint32_t afr[2][2][4];
            #pragma unroll
            for (int kind = 0; kind < 2; ++kind)
                #pragma unroll
                for (int mt = 0; mt < 2; ++mt) {
                    uint32_t addr = (uint32_t)__cvta_generic_to_shared(
                        Ab[kind] + (wm0 + mt*16 + (sec & 1)*8 + (lane & 7)) * 40
                                 + ks + (sec >> 1) * 8);
                    asm volatile(
                        "ldmatrix.sync.aligned.m8n8.x4.shared.b16 {%0,%1,%2,%3}, [%4];"
                        : "=r"(afr[kind][mt][0]), "=r"(afr[kind][mt][1]),
                          "=r"(afr[kind][mt][2]), "=r"(afr[kind][mt][3])
                        : "r"(addr));
                }
            uint32_t bfr[2][8][2];
            #pragma unroll
            for (int kind = 0; kind < 2; ++kind)
                #pragma unroll
                for (int p = 0; p < 4; ++p) {
                    uint32_t addr = (uint32_t)__cvta_generic_to_shared(
                        Bb[kind] + (wn0 + p*16 + (sec >> 1)*8 + (lane & 7)) * 40
                                 + ks + (sec & 1) * 8);
                    asm volatile(
                        "ldmatrix.sync.aligned.m8n8.x4.shared.b16 {%0,%1,%2,%3}, [%4];"
                        : "=r"(bfr[kind][p*2][0]), "=r"(bfr[kind][p*2][1]),
                          "=r"(bfr[kind][p*2+1][0]), "=r"(bfr[kind][p*2+1][1])
                        : "r"(addr));
                }
            #pragma unroll
            for (int mt = 0; mt < 2; ++mt)
                #pragma unroll
                for (int nt = 0; nt < 8; ++nt) {
                    #pragma unroll
                    for (int pr = 0; pr < 3; ++pr) {
                        const int ak = (pr == 2) ? 1 : 0;
                        const int bk = (pr == 1) ? 1 : 0;
                        asm volatile(
                            "mma.sync.aligned.m16n8k16.row.col.f32.bf16.bf16.f32 "
                            "{%0,%1,%2,%3}, {%4,%5,%6,%7}, {%8,%9}, {%0,%1,%2,%3};"
                            : "+f"(acc[mt][nt][0]), "+f"(acc[mt][nt][1]),
                              "+f"(acc[mt][nt][2]), "+f"(acc[mt][nt][3])
                            : "r"(afr[ak][mt][0]), "r"(afr[ak][mt][1]),
                              "r"(afr[ak][mt][2]), "r"(afr[ak][mt][3]),
                              "r"(bfr[bk][nt][0]), "r"(bfr[bk][nt][1]));
                    }
                }
        }
        __syncthreads();
    }

    #pragma unroll
    for (int mt = 0; mt < 2; ++mt) {
        #pragma unroll
        for (int half = 0; half < 2; ++half) {
            int r = r0 + wm0 + mt * 16 + (lane >> 2) + half * 8;
            int tt = r >> 5, bb = r & 31;
            size_t rowoff = ((size_t)(bb * T_ + tt)) * V_;
            #pragma unroll
            for (int nt = 0; nt < 8; ++nt) {
                int v = v0 + wn0 + nt * 8 + (lane & 3) * 2;
                float2 res;
                res.x = acc[mt][nt][half * 2 + 0] + bfc[v];
                res.y = acc[mt][nt][half * 2 + 1] + bfc[v + 1];
                *(float2*)&out[rowoff + v] = res;
            }
        }
    }
}

extern "C" void kernel_launch(void* const* d_in, const int* in_sizes, int n_in,
                              void* d_out, int out_size) {
    const float* src    = (const float*)d_in[0];
    const int*   trg    = (const int*)  d_in[1];
    const float* emb    = (const float*)d_in[2];
    const float* W_ih   = (const float*)d_in[3];
    const float* b_ih   = (const float*)d_in[4];
    const float* W_hh   = (const float*)d_in[5];
    const float* b_hh   = (const float*)d_in[6];
    const float* Wp     = (const float*)d_in[7];
    const float* bp     = (const float*)d_in[8];
    const float* Wah    = (const float*)d_in[9];
    const float* bah    = (const float*)d_in[10];
    const float* Wfc    = (const float*)d_in[11];
    const float* bfc    = (const float*)d_in[12];
    const float* iff    = (const float*)d_in[13];
    const float* hinit  = (const float*)d_in[14];
    float* out = (float*)d_out;

    cudaFuncSetAttribute(step_kernel,
        cudaFuncAttributeMaxDynamicSharedMemorySize, XBYTES);
    cudaFuncSetAttribute(fgemm_kernel,
        cudaFuncAttributeMaxDynamicSharedMemorySize, FG_SMEM);

    init_kernel<<<32, 512>>>(hinit, iff);
    wconv_kernel<<<2048, 256>>>(Wfc);
    qb_kernel<<<256, 256>>>(src, bp);
    qgemm_kernel<<<dim3(H_ / PBN, (B_ * S_) / PBM), 256>>>(src, Wp);
    gtgemm_kernel<<<dim3((B_ * S_) / PBN, H_ / PBM), 256>>>(Wah, src);

    step_kernel<<<NB, NT, XBYTES>>>(trg, emb, W_ih, b_ih, W_hh, b_hh,
                                    Wah, bah, out);

    fgemm_kernel<<<dim3(V_ / 128, (T_ * B_) / 128), 256, FG_SMEM>>>(bfc, out);
}